// round 1
// baseline (speedup 1.0000x reference)
#include <cuda_runtime.h>

// Problem constants
#define B_TOTAL 4096
#define T_TOT   64
#define KDIM    192     // 2*N_COM + N_REAL
#define NCOM    64
#define NREAL   64
#define DT      0.01f

#define MROWS   28      // batch rows per CTA -> 147 CTAs on 148 SMs
#define NTH     224     // 7 warps: warp = row-group of 4, lane = column group
#define YPAD    200     // padded row stride in shared (floats)

// Packed, transposed weights (k-major, n contiguous) -- filled by prep kernel.
__device__ float g_W1T[192 * 192];   // combined [cW1 ; rW1], W1T[k][n]
__device__ float g_W2cT[128 * 128];  // cW2T[k][n]
__device__ float g_W2rT[64 * 64];    // rW2T[k][n]
__device__ float g_b1[192];          // [cb1 ; rb1]
__device__ float g_b2[192];          // [cb2 ; rb2]

__global__ void pack_weights(const float* __restrict__ cW1, const float* __restrict__ cb1,
                             const float* __restrict__ cW2, const float* __restrict__ cb2,
                             const float* __restrict__ rW1, const float* __restrict__ rb1,
                             const float* __restrict__ rW2, const float* __restrict__ rb2)
{
    int i = blockIdx.x * blockDim.x + threadIdx.x;
    if (i < 192 * 192) {
        int k = i / 192, n = i % 192;
        g_W1T[i] = (n < 128) ? cW1[n * 192 + k] : rW1[(n - 128) * 192 + k];
    }
    if (i < 128 * 128) {
        int k = i / 128, n = i % 128;
        g_W2cT[i] = cW2[n * 128 + k];
    }
    if (i < 64 * 64) {
        int k = i / 64, n = i % 64;
        g_W2rT[i] = rW2[n * 64 + k];
    }
    if (i < 192) {
        g_b1[i] = (i < 128) ? cb1[i] : rb1[i - 128];
        g_b2[i] = (i < 128) ? cb2[i] : rb2[i - 128];
    }
}

__global__ __launch_bounds__(NTH, 1)
void koopman_kernel(const float* __restrict__ x, float* __restrict__ out)
{
    __shared__ float y_s[MROWS][YPAD];  // current state, fp32
    __shared__ float h_s[MROWS][YPAD];  // phase-1 output (relu'd), then reused for phase-2 output

    const int tid  = threadIdx.x;
    const int lane = tid & 31;
    const int wg   = tid >> 5;        // row group 0..6
    const int row0 = wg * 4;
    const int b0   = blockIdx.x * MROWS;

    // Load initial state y = x[:, 0, :]; clamp out-of-range rows (writes are guarded).
    for (int idx = tid; idx < MROWS * KDIM; idx += NTH) {
        int m = idx / KDIM, k = idx % KDIM;
        int r = b0 + m; if (r > B_TOTAL - 1) r = B_TOTAL - 1;
        y_s[m][k] = x[(size_t)r * T_TOT * KDIM + k];
    }
    __syncthreads();

    for (int t = 0; t < T_TOT; ++t) {
        // ---------------- Phase 1: h1 = relu(y @ W1T + b1), cols = lane + 32*j ----------------
        {
            float acc[4][6];
            #pragma unroll
            for (int j = 0; j < 6; j++) {
                float b = g_b1[lane + 32 * j];
                #pragma unroll
                for (int i = 0; i < 4; i++) acc[i][j] = b;
            }
            #pragma unroll 4
            for (int k = 0; k < 192; k++) {
                float w[6];
                #pragma unroll
                for (int j = 0; j < 6; j++)
                    w[j] = __ldg(&g_W1T[k * 192 + lane + 32 * j]);
                #pragma unroll
                for (int i = 0; i < 4; i++) {
                    float yv = y_s[row0 + i][k];   // broadcast within warp
                    #pragma unroll
                    for (int j = 0; j < 6; j++)
                        acc[i][j] = fmaf(yv, w[j], acc[i][j]);
                }
            }
            #pragma unroll
            for (int i = 0; i < 4; i++)
                #pragma unroll
                for (int j = 0; j < 6; j++)
                    h_s[row0 + i][lane + 32 * j] = fmaxf(acc[i][j], 0.0f);
        }
        __syncthreads();

        // ---------------- Phase 2: h2 = h1c @ cW2T + cb2  |  r2 = h1r @ rW2T + rb2 ----------------
        {
            float acc[4][6];
            #pragma unroll
            for (int j = 0; j < 6; j++) {
                float b = g_b2[lane + 32 * j];
                #pragma unroll
                for (int i = 0; i < 4; i++) acc[i][j] = b;
            }
            // complex head: cols lane+32j (j<4), K = 128 over h1[:, 0:128]
            #pragma unroll 2
            for (int k = 0; k < 128; k++) {
                float w[4];
                #pragma unroll
                for (int j = 0; j < 4; j++)
                    w[j] = __ldg(&g_W2cT[k * 128 + lane + 32 * j]);
                #pragma unroll
                for (int i = 0; i < 4; i++) {
                    float hv = h_s[row0 + i][k];
                    #pragma unroll
                    for (int j = 0; j < 4; j++)
                        acc[i][j] = fmaf(hv, w[j], acc[i][j]);
                }
            }
            // real head: cols 128+lane, 160+lane (j=4,5), K = 64 over h1[:, 128:192]
            #pragma unroll 2
            for (int k = 0; k < 64; k++) {
                float w4 = __ldg(&g_W2rT[k * 64 + lane]);
                float w5 = __ldg(&g_W2rT[k * 64 + lane + 32]);
                #pragma unroll
                for (int i = 0; i < 4; i++) {
                    float hv = h_s[row0 + i][128 + k];
                    acc[i][4] = fmaf(hv, w4, acc[i][4]);
                    acc[i][5] = fmaf(hv, w5, acc[i][5]);
                }
            }
            __syncthreads();   // everyone done READING h_s before it is overwritten
            #pragma unroll
            for (int i = 0; i < 4; i++)
                #pragma unroll
                for (int j = 0; j < 6; j++)
                    h_s[row0 + i][lane + 32 * j] = acc[i][j];
        }
        __syncthreads();

        // ---------------- Phase 3: Koopman state update + output write ----------------
        // 128 work items per row: 64 rotation pairs + 64 real dims. 28*128 = 3584 = 16 * NTH.
        #pragma unroll 4
        for (int it = 0; it < 16; ++it) {
            int idx = tid + it * NTH;
            int m = idx >> 7;
            int i = idx & 127;
            int r = b0 + m;
            if (i < 64) {
                float mu = h_s[m][2 * i];
                float om = h_s[m][2 * i + 1];
                float e = __expf(DT * mu);
                float c = __cosf(DT * om);
                float s = __sinf(DT * om);
                float ye = y_s[m][2 * i];
                float yo = y_s[m][2 * i + 1];
                float ne = e * (c * ye - s * yo);
                float no = e * (s * ye + c * yo);
                y_s[m][2 * i]     = ne;
                y_s[m][2 * i + 1] = no;
                if (r < B_TOTAL) {
                    float2* p = (float2*)&out[((size_t)r * T_TOT + t) * KDIM + 2 * i];
                    *p = make_float2(ne, no);
                }
            } else {
                int n = i - 64;
                float re = h_s[m][128 + n];
                float v = y_s[m][128 + n] * __expf(DT * re);
                y_s[m][128 + n] = v;
                if (r < B_TOTAL)
                    out[((size_t)r * T_TOT + t) * KDIM + 128 + n] = v;
            }
        }
        __syncthreads();
    }
}

extern "C" void kernel_launch(void* const* d_in, const int* in_sizes, int n_in,
                              void* d_out, int out_size)
{
    const float* x   = (const float*)d_in[0];
    const float* cW1 = (const float*)d_in[1];
    const float* cb1 = (const float*)d_in[2];
    const float* cW2 = (const float*)d_in[3];
    const float* cb2 = (const float*)d_in[4];
    const float* rW1 = (const float*)d_in[5];
    const float* rb1 = (const float*)d_in[6];
    const float* rW2 = (const float*)d_in[7];
    const float* rb2 = (const float*)d_in[8];
    float* out = (float*)d_out;

    // One-time per-launch weight packing (tiny, graph-capturable)
    pack_weights<<<(192 * 192 + 255) / 256, 256>>>(cW1, cb1, cW2, cb2, rW1, rb1, rW2, rb2);

    // Persistent recurrence kernel: 147 CTAs x 224 threads, 28 batch rows each
    int grid = (B_TOTAL + MROWS - 1) / MROWS;   // 147
    koopman_kernel<<<grid, NTH>>>(x, out);
}

// round 2
// speedup vs baseline: 1.4767x; 1.4767x over previous
#include <cuda_runtime.h>
#include <cstdint>

// Problem constants
#define B_TOTAL 4096
#define T_TOT   64
#define KDIM    192     // 2*N_COM + N_REAL
#define DT      0.01f

#define MROWS   28      // batch rows per CTA -> 147 CTAs (148 SMs)
#define NTH     448     // 14 warps; warp w owns rows 2w, 2w+1 for ALL columns
                        // => all intra-step deps are warp-local (no __syncthreads in t-loop)

// Packed, transposed weights (k-major, n contiguous) -- filled by prep kernel.
__device__ float g_W1T[192 * 192];   // combined [cW1 ; rW1], W1T[k][n]
__device__ float g_W2cT[128 * 128];  // cW2T[k][n]
__device__ float g_W2rT[64 * 64];    // rW2T[k][n]
__device__ float g_b1[192];          // [cb1 ; rb1]
__device__ float g_b2[192];          // [cb2 ; rb2]

__global__ void pack_weights(const float* __restrict__ cW1, const float* __restrict__ cb1,
                             const float* __restrict__ cW2, const float* __restrict__ cb2,
                             const float* __restrict__ rW1, const float* __restrict__ rb1,
                             const float* __restrict__ rW2, const float* __restrict__ rb2)
{
    int i = blockIdx.x * blockDim.x + threadIdx.x;
    if (i < 192 * 192) {
        int k = i / 192, n = i % 192;
        g_W1T[i] = (n < 128) ? cW1[n * 192 + k] : rW1[(n - 128) * 192 + k];
    }
    if (i < 128 * 128) {
        int k = i / 128, n = i % 128;
        g_W2cT[i] = cW2[n * 128 + k];
    }
    if (i < 64 * 64) {
        int k = i / 64, n = i % 64;
        g_W2rT[i] = rW2[n * 64 + k];
    }
    if (i < 192) {
        g_b1[i] = (i < 128) ? cb1[i] : rb1[i - 128];
        g_b2[i] = (i < 128) ? cb2[i] : rb2[i - 128];
    }
}

// Packed f32x2 FMA (sm_100+): d = a*b + c elementwise on two packed fp32.
// Numerically identical to two fmaf's (rn rounding per lane).
__device__ __forceinline__ uint64_t ffma2(uint64_t a, uint64_t b, uint64_t c)
{
    uint64_t d;
    asm("fma.rn.f32x2 %0, %1, %2, %3;" : "=l"(d) : "l"(a), "l"(b), "l"(c));
    return d;
}
__device__ __forceinline__ uint64_t pack2(float lo, float hi)
{
    uint64_t r;
    asm("mov.b64 %0, {%1, %2};" : "=l"(r) : "f"(lo), "f"(hi));
    return r;
}
__device__ __forceinline__ void unpack2(uint64_t v, float& lo, float& hi)
{
    asm("mov.b64 {%0, %1}, %2;" : "=f"(lo), "=f"(hi) : "l"(v));
}
__device__ __forceinline__ uint64_t ldg64(const float* p)
{
    return __ldg((const unsigned long long*)p);
}

// Dynamic SMEM layout: two duplicated-pair state arrays.
//   y2[m*192 + c] = (y[m][c], y[m][c]) as uint64   (state)
//   h2[m*192 + c] = (h[m][c], h[m][c])             (MLP intermediate / outputs)
// 28*192*8*2 = 86016 bytes.
#define SMEM_BYTES (MROWS * 192 * 8 * 2)

__global__ __launch_bounds__(NTH, 1)
void koopman_kernel(const float* __restrict__ x, float* __restrict__ out)
{
    extern __shared__ uint64_t smem[];
    uint64_t* y2 = smem;
    uint64_t* h2 = smem + MROWS * 192;

    const int tid  = threadIdx.x;
    const int lane = tid & 31;
    const int wrp  = tid >> 5;         // 0..13
    const int r0   = 2 * wrp;          // this warp's first row
    const int c0   = 2 * lane;         // this lane's base column (pairs at c0+64j)
    const int b0   = blockIdx.x * MROWS;

    // ---- Initial state load: y2[m][k] = dup(x[r][0][k]) ----
    for (int idx = tid; idx < MROWS * KDIM; idx += NTH) {
        int m = idx / KDIM, k = idx % KDIM;
        int r = b0 + m; if (r > B_TOTAL - 1) r = B_TOTAL - 1;
        float v = x[(size_t)r * T_TOT * KDIM + k];
        y2[m * 192 + k] = pack2(v, v);
    }
    __syncthreads();   // only CTA-wide barrier in the kernel

    // Per-lane bias pairs (loop-invariant)
    const uint64_t b1p0 = ldg64(g_b1 + c0);
    const uint64_t b1p1 = ldg64(g_b1 + c0 + 64);
    const uint64_t b1p2 = ldg64(g_b1 + c0 + 128);
    const uint64_t b2p0 = ldg64(g_b2 + c0);
    const uint64_t b2p1 = ldg64(g_b2 + c0 + 64);
    const uint64_t b2p2 = ldg64(g_b2 + c0 + 128);

    const uint64_t* ya_row = y2 + r0 * 192;
    const uint64_t* yb_row = y2 + (r0 + 1) * 192;
    const uint64_t* ha_row = h2 + r0 * 192;
    const uint64_t* hb_row = h2 + (r0 + 1) * 192;

    const int  rA = b0 + r0, rB = b0 + r0 + 1;
    const bool wA = rA < B_TOTAL, wB = rB < B_TOTAL;

    for (int t = 0; t < T_TOT; ++t) {
        // ---------- Phase 1: h1 = relu(y @ W1T + b1)  (K=192, 6 cols/lane as 3 pairs) ----------
        {
            uint64_t a00 = b1p0, a01 = b1p1, a02 = b1p2;
            uint64_t a10 = b1p0, a11 = b1p1, a12 = b1p2;
            #pragma unroll 4
            for (int k = 0; k < 192; ++k) {
                const float* wp = g_W1T + k * 192 + c0;
                uint64_t w0 = ldg64(wp);
                uint64_t w1 = ldg64(wp + 64);
                uint64_t w2 = ldg64(wp + 128);
                uint64_t ya = ya_row[k];          // LDS.64 broadcast (dup pair)
                uint64_t yb = yb_row[k];
                a00 = ffma2(ya, w0, a00); a01 = ffma2(ya, w1, a01); a02 = ffma2(ya, w2, a02);
                a10 = ffma2(yb, w0, a10); a11 = ffma2(yb, w1, a11); a12 = ffma2(yb, w2, a12);
            }
            // relu + duplicated store: float4 (v0,v0,v1,v1) covers pair cols c,c+1
            float v0, v1;
            unpack2(a00, v0, v1);
            *(float4*)(h2 + r0 * 192 + c0)       = make_float4(fmaxf(v0,0.f), fmaxf(v0,0.f), fmaxf(v1,0.f), fmaxf(v1,0.f));
            unpack2(a01, v0, v1);
            *(float4*)(h2 + r0 * 192 + c0 + 64)  = make_float4(fmaxf(v0,0.f), fmaxf(v0,0.f), fmaxf(v1,0.f), fmaxf(v1,0.f));
            unpack2(a02, v0, v1);
            *(float4*)(h2 + r0 * 192 + c0 + 128) = make_float4(fmaxf(v0,0.f), fmaxf(v0,0.f), fmaxf(v1,0.f), fmaxf(v1,0.f));
            unpack2(a10, v0, v1);
            *(float4*)(h2 + (r0+1) * 192 + c0)       = make_float4(fmaxf(v0,0.f), fmaxf(v0,0.f), fmaxf(v1,0.f), fmaxf(v1,0.f));
            unpack2(a11, v0, v1);
            *(float4*)(h2 + (r0+1) * 192 + c0 + 64)  = make_float4(fmaxf(v0,0.f), fmaxf(v0,0.f), fmaxf(v1,0.f), fmaxf(v1,0.f));
            unpack2(a12, v0, v1);
            *(float4*)(h2 + (r0+1) * 192 + c0 + 128) = make_float4(fmaxf(v0,0.f), fmaxf(v0,0.f), fmaxf(v1,0.f), fmaxf(v1,0.f));
        }
        __syncwarp();   // warp-local h2 ready

        // ---------- Phase 2: h2c = h1c@cW2T + cb2 | h2r = h1r@rW2T + rb2 ----------
        {
            uint64_t a00 = b2p0, a01 = b2p1, a02 = b2p2;
            uint64_t a10 = b2p0, a11 = b2p1, a12 = b2p2;
            #pragma unroll 2
            for (int k = 0; k < 64; ++k) {
                // complex head, k
                {
                    const float* wp = g_W2cT + k * 128 + c0;
                    uint64_t w0 = ldg64(wp), w1 = ldg64(wp + 64);
                    uint64_t ha = ha_row[k], hb = hb_row[k];
                    a00 = ffma2(ha, w0, a00); a01 = ffma2(ha, w1, a01);
                    a10 = ffma2(hb, w0, a10); a11 = ffma2(hb, w1, a11);
                }
                // complex head, k+64
                {
                    const float* wp = g_W2cT + (k + 64) * 128 + c0;
                    uint64_t w0 = ldg64(wp), w1 = ldg64(wp + 64);
                    uint64_t ha = ha_row[k + 64], hb = hb_row[k + 64];
                    a00 = ffma2(ha, w0, a00); a01 = ffma2(ha, w1, a01);
                    a10 = ffma2(hb, w0, a10); a11 = ffma2(hb, w1, a11);
                }
                // real head, k
                {
                    uint64_t w2 = ldg64(g_W2rT + k * 64 + c0);
                    uint64_t ha = ha_row[128 + k], hb = hb_row[128 + k];
                    a02 = ffma2(ha, w2, a02);
                    a12 = ffma2(hb, w2, a12);
                }
            }
            __syncwarp();   // all lanes done READING h2 before overwrite
            float v0, v1;
            unpack2(a00, v0, v1); *(float4*)(h2 + r0*192 + c0)           = make_float4(v0, v0, v1, v1);
            unpack2(a01, v0, v1); *(float4*)(h2 + r0*192 + c0 + 64)      = make_float4(v0, v0, v1, v1);
            unpack2(a02, v0, v1); *(float4*)(h2 + r0*192 + c0 + 128)     = make_float4(v0, v0, v1, v1);
            unpack2(a10, v0, v1); *(float4*)(h2 + (r0+1)*192 + c0)       = make_float4(v0, v0, v1, v1);
            unpack2(a11, v0, v1); *(float4*)(h2 + (r0+1)*192 + c0 + 64)  = make_float4(v0, v0, v1, v1);
            unpack2(a12, v0, v1); *(float4*)(h2 + (r0+1)*192 + c0 + 128) = make_float4(v0, v0, v1, v1);
        }
        __syncwarp();

        // ---------- Phase 3: Koopman update + output (warp-local rows) ----------
        {
            const float* h2f = (const float*)h2;
            const float* y2f = (const float*)y2;
            #pragma unroll
            for (int row = 0; row < 2; ++row) {
                int m = r0 + row;
                int r = row ? rB : rA;
                bool wr = row ? wB : wA;
                int base = m * 192;
                #pragma unroll
                for (int u = 0; u < 2; ++u) {
                    int i = lane + 32 * u;      // rotation pair index, and real index
                    // rotation block 2x2
                    float mu = h2f[(base + 2*i)     << 1];
                    float om = h2f[(base + 2*i + 1) << 1];
                    float e = __expf(DT * mu);
                    float c = __cosf(DT * om);
                    float s = __sinf(DT * om);
                    float ye = y2f[(base + 2*i)     << 1];
                    float yo = y2f[(base + 2*i + 1) << 1];
                    float ne = e * (c * ye - s * yo);
                    float no = e * (s * ye + c * yo);
                    y2[base + 2*i]     = pack2(ne, ne);
                    y2[base + 2*i + 1] = pack2(no, no);
                    if (wr) *(float2*)&out[((size_t)r * T_TOT + t) * KDIM + 2*i] = make_float2(ne, no);
                    // real diagonal
                    float re = h2f[(base + 128 + i) << 1];
                    float v  = y2f[(base + 128 + i) << 1] * __expf(DT * re);
                    y2[base + 128 + i] = pack2(v, v);
                    if (wr) out[((size_t)r * T_TOT + t) * KDIM + 128 + i] = v;
                }
            }
        }
        __syncwarp();   // y2 updated for next step's phase 1
    }
}

extern "C" void kernel_launch(void* const* d_in, const int* in_sizes, int n_in,
                              void* d_out, int out_size)
{
    const float* x   = (const float*)d_in[0];
    const float* cW1 = (const float*)d_in[1];
    const float* cb1 = (const float*)d_in[2];
    const float* cW2 = (const float*)d_in[3];
    const float* cb2 = (const float*)d_in[4];
    const float* rW1 = (const float*)d_in[5];
    const float* rb1 = (const float*)d_in[6];
    const float* rW2 = (const float*)d_in[7];
    const float* rb2 = (const float*)d_in[8];
    float* out = (float*)d_out;

    pack_weights<<<(192 * 192 + 255) / 256, 256>>>(cW1, cb1, cW2, cb2, rW1, rb1, rW2, rb2);

    cudaFuncSetAttribute(koopman_kernel, cudaFuncAttributeMaxDynamicSharedMemorySize, SMEM_BYTES);
    int grid = (B_TOTAL + MROWS - 1) / MROWS;   // 147
    koopman_kernel<<<grid, NTH, SMEM_BYTES>>>(x, out);
}

// round 3
// speedup vs baseline: 1.5025x; 1.0175x over previous
#include <cuda_runtime.h>
#include <cstdint>

// Problem constants
#define B_TOTAL 4096
#define T_TOT   64
#define KDIM    192     // 2*N_COM + N_REAL
#define DT      0.01f

#define MROWS   28      // batch rows per CTA -> 147 CTAs (148 SMs, one wave)
#define NTH     224     // 7 warps; warp w owns rows 4w..4w+3 for ALL columns
#define R       4       // rows per warp: weight LDG amortized over 4 rows

// Packed, transposed weights (k-major, n contiguous) -- filled by prep kernel.
__device__ float g_W1T[192 * 192];   // combined [cW1 ; rW1], W1T[k][n]
__device__ float g_W2cT[128 * 128];  // cW2T[k][n]
__device__ float g_W2rT[64 * 64];    // rW2T[k][n]
__device__ float g_b1[192];          // [cb1 ; rb1]
__device__ float g_b2[192];          // [cb2 ; rb2]

__global__ void pack_weights(const float* __restrict__ cW1, const float* __restrict__ cb1,
                             const float* __restrict__ cW2, const float* __restrict__ cb2,
                             const float* __restrict__ rW1, const float* __restrict__ rb1,
                             const float* __restrict__ rW2, const float* __restrict__ rb2)
{
    int i = blockIdx.x * blockDim.x + threadIdx.x;
    if (i < 192 * 192) {
        int k = i / 192, n = i % 192;
        g_W1T[i] = (n < 128) ? cW1[n * 192 + k] : rW1[(n - 128) * 192 + k];
    }
    if (i < 128 * 128) {
        int k = i / 128, n = i % 128;
        g_W2cT[i] = cW2[n * 128 + k];
    }
    if (i < 64 * 64) {
        int k = i / 64, n = i % 64;
        g_W2rT[i] = rW2[n * 64 + k];
    }
    if (i < 192) {
        g_b1[i] = (i < 128) ? cb1[i] : rb1[i - 128];
        g_b2[i] = (i < 128) ? cb2[i] : rb2[i - 128];
    }
}

// Packed f32x2 FMA (sm_100+): d = a*b + c elementwise; bit-exact vs two fmaf's.
__device__ __forceinline__ uint64_t ffma2(uint64_t a, uint64_t b, uint64_t c)
{
    uint64_t d;
    asm("fma.rn.f32x2 %0, %1, %2, %3;" : "=l"(d) : "l"(a), "l"(b), "l"(c));
    return d;
}
__device__ __forceinline__ uint64_t pack2(float lo, float hi)
{
    uint64_t r;
    asm("mov.b64 %0, {%1, %2};" : "=l"(r) : "f"(lo), "f"(hi));
    return r;
}
__device__ __forceinline__ void unpack2(uint64_t v, float& lo, float& hi)
{
    asm("mov.b64 {%0, %1}, %2;" : "=f"(lo), "=f"(hi) : "l"(v));
}
__device__ __forceinline__ uint64_t ldg64(const float* p)
{
    return __ldg((const unsigned long long*)p);
}

// Dynamic SMEM: duplicated-pair state arrays (dup = ffma2 broadcast operand).
//   y2[m*192 + c] = (y[m][c], y[m][c])   h2 likewise.  28*192*8*2 = 86016 B.
#define SMEM_BYTES (MROWS * 192 * 8 * 2)

__global__ __launch_bounds__(NTH, 1)
void koopman_kernel(const float* __restrict__ x, float* __restrict__ out)
{
    extern __shared__ uint64_t smem[];
    uint64_t* y2 = smem;
    uint64_t* h2 = smem + MROWS * 192;

    const int tid  = threadIdx.x;
    const int lane = tid & 31;
    const int wrp  = tid >> 5;         // 0..6
    const int r0   = R * wrp;          // first of this warp's 4 rows
    const int c0   = 2 * lane;         // lane's base column (pairs at c0 + 64j)
    const int b0   = blockIdx.x * MROWS;

    // ---- Initial state load: y2[m][k] = dup(x[r][0][k]) ----
    for (int idx = tid; idx < MROWS * KDIM; idx += NTH) {
        int m = idx / KDIM, k = idx % KDIM;
        int r = b0 + m; if (r > B_TOTAL - 1) r = B_TOTAL - 1;
        float v = x[(size_t)r * T_TOT * KDIM + k];
        y2[m * 192 + k] = pack2(v, v);
    }
    __syncthreads();   // only CTA-wide barrier

    // Loop-invariant bias pairs
    const uint64_t b1p[3] = { ldg64(g_b1 + c0), ldg64(g_b1 + c0 + 64), ldg64(g_b1 + c0 + 128) };
    const uint64_t b2p[3] = { ldg64(g_b2 + c0), ldg64(g_b2 + c0 + 64), ldg64(g_b2 + c0 + 128) };

    const float* w1base  = g_W1T  + c0;
    const float* w2cbase = g_W2cT + c0;
    const float* w2rbase = g_W2rT + c0;

    const uint64_t* yrow[R];
    const uint64_t* hrow[R];
    int   gr[R];
    bool  wr[R];
    #pragma unroll
    for (int i = 0; i < R; i++) {
        yrow[i] = y2 + (r0 + i) * 192;
        hrow[i] = h2 + (r0 + i) * 192;
        gr[i]   = b0 + r0 + i;
        wr[i]   = gr[i] < B_TOTAL;
    }

    for (int t = 0; t < T_TOT; ++t) {
        // ---------- Phase 1: h1 = relu(y @ W1T + b1)  (K=192, 3 col-pairs x 4 rows) ----------
        {
            uint64_t acc[R][3];
            #pragma unroll
            for (int i = 0; i < R; i++)
                #pragma unroll
                for (int j = 0; j < 3; j++) acc[i][j] = b1p[j];

            #pragma unroll 4
            for (int k = 0; k < 192; ++k) {
                const float* wp = w1base + k * 192;
                uint64_t w0 = ldg64(wp);
                uint64_t w1 = ldg64(wp + 64);
                uint64_t w2 = ldg64(wp + 128);
                #pragma unroll
                for (int i = 0; i < R; i++) {
                    uint64_t yv = yrow[i][k];      // LDS.64 broadcast (dup pair)
                    acc[i][0] = ffma2(yv, w0, acc[i][0]);
                    acc[i][1] = ffma2(yv, w1, acc[i][1]);
                    acc[i][2] = ffma2(yv, w2, acc[i][2]);
                }
            }
            #pragma unroll
            for (int i = 0; i < R; i++) {
                #pragma unroll
                for (int j = 0; j < 3; j++) {
                    float v0, v1; unpack2(acc[i][j], v0, v1);
                    v0 = fmaxf(v0, 0.f); v1 = fmaxf(v1, 0.f);
                    *(float4*)(h2 + (r0 + i) * 192 + c0 + 64 * j) = make_float4(v0, v0, v1, v1);
                }
            }
        }
        __syncwarp();   // warp-local h2 ready

        // ---------- Phase 2: h2c = h1c@cW2T + cb2 | h2r = h1r@rW2T + rb2 ----------
        {
            uint64_t acc[R][3];
            #pragma unroll
            for (int i = 0; i < R; i++)
                #pragma unroll
                for (int j = 0; j < 3; j++) acc[i][j] = b2p[j];

            #pragma unroll 2
            for (int k = 0; k < 64; ++k) {
                // complex head, k and k+64 ; real head, k
                const float* wpA = w2cbase + k * 128;
                const float* wpB = w2cbase + (k + 64) * 128;
                uint64_t wA0 = ldg64(wpA), wA1 = ldg64(wpA + 64);
                uint64_t wB0 = ldg64(wpB), wB1 = ldg64(wpB + 64);
                uint64_t wR  = ldg64(w2rbase + k * 64);
                #pragma unroll
                for (int i = 0; i < R; i++) {
                    uint64_t hA = hrow[i][k];
                    uint64_t hB = hrow[i][k + 64];
                    uint64_t hR = hrow[i][128 + k];
                    acc[i][0] = ffma2(hA, wA0, acc[i][0]);
                    acc[i][1] = ffma2(hA, wA1, acc[i][1]);
                    acc[i][0] = ffma2(hB, wB0, acc[i][0]);
                    acc[i][1] = ffma2(hB, wB1, acc[i][1]);
                    acc[i][2] = ffma2(hR, wR,  acc[i][2]);
                }
            }
            __syncwarp();   // all lanes done READING h2 before overwrite
            #pragma unroll
            for (int i = 0; i < R; i++) {
                #pragma unroll
                for (int j = 0; j < 3; j++) {
                    float v0, v1; unpack2(acc[i][j], v0, v1);
                    *(float4*)(h2 + (r0 + i) * 192 + c0 + 64 * j) = make_float4(v0, v0, v1, v1);
                }
            }
        }
        __syncwarp();

        // ---------- Phase 3: Koopman update + output (warp-local rows) ----------
        {
            const float* h2f = (const float*)h2;
            const float* y2f = (const float*)y2;
            #pragma unroll
            for (int row = 0; row < R; ++row) {
                int m = r0 + row;
                int base = m * 192;
                #pragma unroll
                for (int u = 0; u < 2; ++u) {
                    int i = lane + 32 * u;      // rotation pair index & real index
                    float mu = h2f[(base + 2 * i)     << 1];
                    float om = h2f[(base + 2 * i + 1) << 1];
                    float e = __expf(DT * mu);
                    float c = __cosf(DT * om);
                    float s = __sinf(DT * om);
                    float ye = y2f[(base + 2 * i)     << 1];
                    float yo = y2f[(base + 2 * i + 1) << 1];
                    float ne = e * (c * ye - s * yo);
                    float no = e * (s * ye + c * yo);
                    y2[base + 2 * i]     = pack2(ne, ne);
                    y2[base + 2 * i + 1] = pack2(no, no);
                    if (wr[row]) *(float2*)&out[((size_t)gr[row] * T_TOT + t) * KDIM + 2 * i] = make_float2(ne, no);
                    float re = h2f[(base + 128 + i) << 1];
                    float v  = y2f[(base + 128 + i) << 1] * __expf(DT * re);
                    y2[base + 128 + i] = pack2(v, v);
                    if (wr[row]) out[((size_t)gr[row] * T_TOT + t) * KDIM + 128 + i] = v;
                }
            }
        }
        __syncwarp();   // y2 updated for next step's phase 1
    }
}

extern "C" void kernel_launch(void* const* d_in, const int* in_sizes, int n_in,
                              void* d_out, int out_size)
{
    const float* x   = (const float*)d_in[0];
    const float* cW1 = (const float*)d_in[1];
    const float* cb1 = (const float*)d_in[2];
    const float* cW2 = (const float*)d_in[3];
    const float* cb2 = (const float*)d_in[4];
    const float* rW1 = (const float*)d_in[5];
    const float* rb1 = (const float*)d_in[6];
    const float* rW2 = (const float*)d_in[7];
    const float* rb2 = (const float*)d_in[8];
    float* out = (float*)d_out;

    pack_weights<<<(192 * 192 + 255) / 256, 256>>>(cW1, cb1, cW2, cb2, rW1, rb1, rW2, rb2);

    cudaFuncSetAttribute(koopman_kernel, cudaFuncAttributeMaxDynamicSharedMemorySize, SMEM_BYTES);
    int grid = (B_TOTAL + MROWS - 1) / MROWS;   // 147
    koopman_kernel<<<grid, NTH, SMEM_BYTES>>>(x, out);
}

// round 4
// speedup vs baseline: 1.5883x; 1.0571x over previous
#include <cuda_runtime.h>
#include <cstdint>

// Problem constants
#define B_TOTAL 4096
#define T_TOT   64
#define KDIM    192     // 2*N_COM + N_REAL
#define DT      0.01f

#define MROWS   28      // batch rows per CTA -> 147 CTAs (148 SMs, one wave)
#define NTH     672     // 21 warps = 7 row-groups (4 rows) x 3 col-groups (64 cols)
#define R       4       // rows per warp

// Packed, transposed weights (k-major, n contiguous) -- filled by prep kernel.
__device__ float g_W1T[192 * 192];   // combined [cW1 ; rW1], W1T[k][n]
__device__ float g_W2cT[128 * 128];  // cW2T[k][n]
__device__ float g_W2rT[64 * 64];    // rW2T[k][n]
__device__ float g_b1[192];          // [cb1 ; rb1]
__device__ float g_b2[192];          // [cb2 ; rb2]

__global__ void pack_weights(const float* __restrict__ cW1, const float* __restrict__ cb1,
                             const float* __restrict__ cW2, const float* __restrict__ cb2,
                             const float* __restrict__ rW1, const float* __restrict__ rb1,
                             const float* __restrict__ rW2, const float* __restrict__ rb2)
{
    int i = blockIdx.x * blockDim.x + threadIdx.x;
    if (i < 192 * 192) {
        int k = i / 192, n = i % 192;
        g_W1T[i] = (n < 128) ? cW1[n * 192 + k] : rW1[(n - 128) * 192 + k];
    }
    if (i < 128 * 128) {
        int k = i / 128, n = i % 128;
        g_W2cT[i] = cW2[n * 128 + k];
    }
    if (i < 64 * 64) {
        int k = i / 64, n = i % 64;
        g_W2rT[i] = rW2[n * 64 + k];
    }
    if (i < 192) {
        g_b1[i] = (i < 128) ? cb1[i] : rb1[i - 128];
        g_b2[i] = (i < 128) ? cb2[i] : rb2[i - 128];
    }
}

// Packed f32x2 FMA (sm_100+): d = a*b + c elementwise; bit-exact vs two fmaf's.
__device__ __forceinline__ uint64_t ffma2(uint64_t a, uint64_t b, uint64_t c)
{
    uint64_t d;
    asm("fma.rn.f32x2 %0, %1, %2, %3;" : "=l"(d) : "l"(a), "l"(b), "l"(c));
    return d;
}
__device__ __forceinline__ uint64_t pack2(float lo, float hi)
{
    uint64_t r;
    asm("mov.b64 %0, {%1, %2};" : "=l"(r) : "f"(lo), "f"(hi));
    return r;
}
__device__ __forceinline__ void unpack2(uint64_t v, float& lo, float& hi)
{
    asm("mov.b64 {%0, %1}, %2;" : "=f"(lo), "=f"(hi) : "l"(v));
}
__device__ __forceinline__ uint64_t ldg64(const float* p)
{
    return __ldg((const unsigned long long*)p);
}

// Dynamic SMEM: three duplicated-pair arrays (dup = ffma2 broadcast operand).
//   y2 : state          hA : phase-1 out (relu)        hB : phase-2 out
// Each 28*192 u64 = 43008 B; total 129024 B.
#define ARR_U64    (MROWS * 192)
#define SMEM_BYTES (3 * ARR_U64 * 8)

__global__ __launch_bounds__(NTH, 1)
void koopman_kernel(const float* __restrict__ x, float* __restrict__ out)
{
    extern __shared__ uint64_t smem[];
    uint64_t* y2 = smem;
    uint64_t* hA = smem + ARR_U64;
    uint64_t* hB = smem + 2 * ARR_U64;

    const int tid  = threadIdx.x;
    const int lane = tid & 31;
    const int wrp  = tid >> 5;         // 0..20
    const int rowg = wrp % 7;          // row group
    const int colg = wrp / 7;          // column group (0,1,2)
    const int r0   = R * rowg;
    const int cc   = 64 * colg + 2 * lane;   // this lane's output column pair
    const int b0   = blockIdx.x * MROWS;

    // ---- Initial state load: y2[m][k] = dup(x[r][0][k]) ----
    for (int idx = tid; idx < MROWS * KDIM; idx += NTH) {
        int m = idx / KDIM, k = idx % KDIM;
        int r = b0 + m; if (r > B_TOTAL - 1) r = B_TOTAL - 1;
        float v = x[(size_t)r * T_TOT * KDIM + k];
        y2[m * 192 + k] = pack2(v, v);
    }

    // Loop-invariant bias pairs for this lane's columns
    const uint64_t b1p = ldg64(g_b1 + cc);
    const uint64_t b2p = (colg < 2) ? ldg64(g_b2 + cc) : ldg64(g_b2 + 128 + 2 * lane);

    const float* w1p  = g_W1T + cc;                    // stride 192 per k
    const float* w2p  = (colg < 2) ? (g_W2cT + cc)     // stride 128 per k
                                   : (g_W2rT + 2 * lane); // stride 64 per k

    __syncthreads();

    for (int t = 0; t < T_TOT; ++t) {
        // ---------- Phase 1: hA = relu(y @ W1T + b1) ----------
        {
            uint64_t a0 = b1p, a1 = b1p, a2 = b1p, a3 = b1p;
            #pragma unroll 4
            for (int k = 0; k < 192; k += 2) {
                uint64_t wA = ldg64(w1p + k * 192);
                uint64_t wB = ldg64(w1p + (k + 1) * 192);
                ulonglong2 y0 = *(const ulonglong2*)&y2[(r0 + 0) * 192 + k];  // LDS.128
                ulonglong2 y1 = *(const ulonglong2*)&y2[(r0 + 1) * 192 + k];
                ulonglong2 y2v = *(const ulonglong2*)&y2[(r0 + 2) * 192 + k];
                ulonglong2 y3 = *(const ulonglong2*)&y2[(r0 + 3) * 192 + k];
                a0 = ffma2(y0.x, wA, a0);  a0 = ffma2(y0.y, wB, a0);
                a1 = ffma2(y1.x, wA, a1);  a1 = ffma2(y1.y, wB, a1);
                a2 = ffma2(y2v.x, wA, a2); a2 = ffma2(y2v.y, wB, a2);
                a3 = ffma2(y3.x, wA, a3);  a3 = ffma2(y3.y, wB, a3);
            }
            uint64_t acc[R] = { a0, a1, a2, a3 };
            #pragma unroll
            for (int i = 0; i < R; i++) {
                float v0, v1; unpack2(acc[i], v0, v1);
                v0 = fmaxf(v0, 0.f); v1 = fmaxf(v1, 0.f);
                *(float4*)(hA + (r0 + i) * 192 + cc) = make_float4(v0, v0, v1, v1);
            }
        }
        __syncthreads();   // hA ready CTA-wide

        // ---------- Phase 2: hB = [h1c @ cW2T + cb2 | h1r @ rW2T + rb2] ----------
        {
            uint64_t a0 = b2p, a1 = b2p, a2 = b2p, a3 = b2p;
            if (colg < 2) {
                // complex head: K = 128 over hA[:, 0:128], weight stride 128
                #pragma unroll 4
                for (int k = 0; k < 128; k += 2) {
                    uint64_t wA = ldg64(w2p + k * 128);
                    uint64_t wB = ldg64(w2p + (k + 1) * 128);
                    ulonglong2 h0 = *(const ulonglong2*)&hA[(r0 + 0) * 192 + k];
                    ulonglong2 h1 = *(const ulonglong2*)&hA[(r0 + 1) * 192 + k];
                    ulonglong2 h2v = *(const ulonglong2*)&hA[(r0 + 2) * 192 + k];
                    ulonglong2 h3 = *(const ulonglong2*)&hA[(r0 + 3) * 192 + k];
                    a0 = ffma2(h0.x, wA, a0);  a0 = ffma2(h0.y, wB, a0);
                    a1 = ffma2(h1.x, wA, a1);  a1 = ffma2(h1.y, wB, a1);
                    a2 = ffma2(h2v.x, wA, a2); a2 = ffma2(h2v.y, wB, a2);
                    a3 = ffma2(h3.x, wA, a3);  a3 = ffma2(h3.y, wB, a3);
                }
            } else {
                // real head: K = 64 over hA[:, 128:192], weight stride 64
                #pragma unroll 4
                for (int k = 0; k < 64; k += 2) {
                    uint64_t wA = ldg64(w2p + k * 64);
                    uint64_t wB = ldg64(w2p + (k + 1) * 64);
                    ulonglong2 h0 = *(const ulonglong2*)&hA[(r0 + 0) * 192 + 128 + k];
                    ulonglong2 h1 = *(const ulonglong2*)&hA[(r0 + 1) * 192 + 128 + k];
                    ulonglong2 h2v = *(const ulonglong2*)&hA[(r0 + 2) * 192 + 128 + k];
                    ulonglong2 h3 = *(const ulonglong2*)&hA[(r0 + 3) * 192 + 128 + k];
                    a0 = ffma2(h0.x, wA, a0);  a0 = ffma2(h0.y, wB, a0);
                    a1 = ffma2(h1.x, wA, a1);  a1 = ffma2(h1.y, wB, a1);
                    a2 = ffma2(h2v.x, wA, a2); a2 = ffma2(h2v.y, wB, a2);
                    a3 = ffma2(h3.x, wA, a3);  a3 = ffma2(h3.y, wB, a3);
                }
            }
            int oc = (colg < 2) ? cc : (128 + 2 * lane);
            uint64_t acc[R] = { a0, a1, a2, a3 };
            #pragma unroll
            for (int i = 0; i < R; i++) {
                float v0, v1; unpack2(acc[i], v0, v1);
                *(float4*)(hB + (r0 + i) * 192 + oc) = make_float4(v0, v0, v1, v1);
            }
        }
        __syncthreads();   // hB ready CTA-wide

        // ---------- Phase 3: Koopman update + output (CTA-strided) ----------
        {
            const float* hBf = (const float*)hB;
            const float* y2f = (const float*)y2;
            for (int idx = tid; idx < MROWS * 128; idx += NTH) {
                int m = idx >> 7;
                int i = idx & 127;
                int r = b0 + m;
                int base = m * 192;
                if (i < 64) {
                    float mu = hBf[(base + 2 * i)     << 1];
                    float om = hBf[(base + 2 * i + 1) << 1];
                    float e = __expf(DT * mu);
                    float c = __cosf(DT * om);
                    float s = __sinf(DT * om);
                    float ye = y2f[(base + 2 * i)     << 1];
                    float yo = y2f[(base + 2 * i + 1) << 1];
                    float ne = e * (c * ye - s * yo);
                    float no = e * (s * ye + c * yo);
                    y2[base + 2 * i]     = pack2(ne, ne);
                    y2[base + 2 * i + 1] = pack2(no, no);
                    if (r < B_TOTAL)
                        *(float2*)&out[((size_t)r * T_TOT + t) * KDIM + 2 * i] = make_float2(ne, no);
                } else {
                    int n = i - 64;
                    float re = hBf[(base + 128 + n) << 1];
                    float v  = y2f[(base + 128 + n) << 1] * __expf(DT * re);
                    y2[base + 128 + n] = pack2(v, v);
                    if (r < B_TOTAL)
                        out[((size_t)r * T_TOT + t) * KDIM + 128 + n] = v;
                }
            }
        }
        __syncthreads();   // y2 ready for next step
    }
}

extern "C" void kernel_launch(void* const* d_in, const int* in_sizes, int n_in,
                              void* d_out, int out_size)
{
    const float* x   = (const float*)d_in[0];
    const float* cW1 = (const float*)d_in[1];
    const float* cb1 = (const float*)d_in[2];
    const float* cW2 = (const float*)d_in[3];
    const float* cb2 = (const float*)d_in[4];
    const float* rW1 = (const float*)d_in[5];
    const float* rb1 = (const float*)d_in[6];
    const float* rW2 = (const float*)d_in[7];
    const float* rb2 = (const float*)d_in[8];
    float* out = (float*)d_out;

    pack_weights<<<(192 * 192 + 255) / 256, 256>>>(cW1, cb1, cW2, cb2, rW1, rb1, rW2, rb2);

    cudaFuncSetAttribute(koopman_kernel, cudaFuncAttributeMaxDynamicSharedMemorySize, SMEM_BYTES);
    int grid = (B_TOTAL + MROWS - 1) / MROWS;   // 147
    koopman_kernel<<<grid, NTH, SMEM_BYTES>>>(x, out);
}

// round 5
// speedup vs baseline: 1.5907x; 1.0015x over previous
#include <cuda_runtime.h>
#include <cstdint>

// Problem constants
#define B_TOTAL 4096
#define T_TOT   64
#define KDIM    192     // 2*N_COM + N_REAL
#define DT      0.01f

#define MROWS   28      // batch rows per CTA -> 147 CTAs (148 SMs, one wave)
#define NTH     672     // 21 warps = 7 row-groups (4 rows) x 3 col-groups (64 cols)
#define R       4       // rows per warp

// Packed, transposed weights (k-major, n contiguous) -- filled by prep kernel.
__device__ float g_W1T[192 * 192];   // combined [cW1 ; rW1], W1T[k][n]
__device__ float g_W2cT[128 * 128];  // cW2T[k][n]
__device__ float g_W2rT[64 * 64];    // rW2T[k][n]
__device__ float g_b1[192];          // [cb1 ; rb1]
__device__ float g_b2[192];          // [cb2 ; rb2]

__global__ void pack_weights(const float* __restrict__ cW1, const float* __restrict__ cb1,
                             const float* __restrict__ cW2, const float* __restrict__ cb2,
                             const float* __restrict__ rW1, const float* __restrict__ rb1,
                             const float* __restrict__ rW2, const float* __restrict__ rb2)
{
    int i = blockIdx.x * blockDim.x + threadIdx.x;
    if (i < 192 * 192) {
        int k = i / 192, n = i % 192;
        g_W1T[i] = (n < 128) ? cW1[n * 192 + k] : rW1[(n - 128) * 192 + k];
    }
    if (i < 128 * 128) {
        int k = i / 128, n = i % 128;
        g_W2cT[i] = cW2[n * 128 + k];
    }
    if (i < 64 * 64) {
        int k = i / 64, n = i % 64;
        g_W2rT[i] = rW2[n * 64 + k];
    }
    if (i < 192) {
        g_b1[i] = (i < 128) ? cb1[i] : rb1[i - 128];
        g_b2[i] = (i < 128) ? cb2[i] : rb2[i - 128];
    }
}

// Packed f32x2 FMA (sm_100+): d = a*b + c elementwise; bit-exact vs two fmaf's.
__device__ __forceinline__ uint64_t ffma2(uint64_t a, uint64_t b, uint64_t c)
{
    uint64_t d;
    asm("fma.rn.f32x2 %0, %1, %2, %3;" : "=l"(d) : "l"(a), "l"(b), "l"(c));
    return d;
}
__device__ __forceinline__ uint64_t pack2(float lo, float hi)
{
    uint64_t r;
    asm("mov.b64 %0, {%1, %2};" : "=l"(r) : "f"(lo), "f"(hi));
    return r;
}
__device__ __forceinline__ void unpack2(uint64_t v, float& lo, float& hi)
{
    asm("mov.b64 {%0, %1}, %2;" : "=f"(lo), "=f"(hi) : "l"(v));
}
__device__ __forceinline__ uint64_t ldg64(const float* p)
{
    return __ldg((const unsigned long long*)p);
}

// Dynamic SMEM: three duplicated-pair arrays (dup = ffma2 broadcast operand).
//   y2 : state          hA : phase-1 out (relu)        hB : phase-2 out
// Each 28*192 u64 = 43008 B; total 129024 B.
#define ARR_U64    (MROWS * 192)
#define SMEM_BYTES (3 * ARR_U64 * 8)

__global__ __launch_bounds__(NTH, 1)
void koopman_kernel(const float* __restrict__ x, float* __restrict__ out)
{
    extern __shared__ uint64_t smem[];
    uint64_t* y2 = smem;
    uint64_t* hA = smem + ARR_U64;
    uint64_t* hB = smem + 2 * ARR_U64;

    const int tid  = threadIdx.x;
    const int lane = tid & 31;
    const int wrp  = tid >> 5;         // 0..20
    const int rowg = wrp % 7;          // row group
    const int colg = wrp / 7;          // column group (0,1,2)
    const int r0   = R * rowg;
    const int cc   = 64 * colg + 2 * lane;   // this lane's output column pair
    const int b0   = blockIdx.x * MROWS;

    // ---- Initial state load: y2[m][k] = dup(x[r][0][k]) ----
    for (int idx = tid; idx < MROWS * KDIM; idx += NTH) {
        int m = idx / KDIM, k = idx % KDIM;
        int r = b0 + m; if (r > B_TOTAL - 1) r = B_TOTAL - 1;
        float v = x[(size_t)r * T_TOT * KDIM + k];
        y2[m * 192 + k] = pack2(v, v);
    }

    // Loop-invariant bias pairs for this lane's columns
    const uint64_t b1p = ldg64(g_b1 + cc);
    const uint64_t b2p = (colg < 2) ? ldg64(g_b2 + cc) : ldg64(g_b2 + 128 + 2 * lane);

    const float* w1p  = g_W1T + cc;                    // stride 192 per k
    const float* w2p  = (colg < 2) ? (g_W2cT + cc)     // stride 128 per k
                                   : (g_W2rT + 2 * lane); // stride 64 per k

    __syncthreads();

    for (int t = 0; t < T_TOT; ++t) {
        // ---------- Phase 1: hA = relu(y @ W1T + b1) ----------
        {
            uint64_t a0 = b1p, a1 = b1p, a2 = b1p, a3 = b1p;
            #pragma unroll 4
            for (int k = 0; k < 192; k += 2) {
                uint64_t wA = ldg64(w1p + k * 192);
                uint64_t wB = ldg64(w1p + (k + 1) * 192);
                ulonglong2 y0 = *(const ulonglong2*)&y2[(r0 + 0) * 192 + k];  // LDS.128
                ulonglong2 y1 = *(const ulonglong2*)&y2[(r0 + 1) * 192 + k];
                ulonglong2 y2v = *(const ulonglong2*)&y2[(r0 + 2) * 192 + k];
                ulonglong2 y3 = *(const ulonglong2*)&y2[(r0 + 3) * 192 + k];
                a0 = ffma2(y0.x, wA, a0);  a0 = ffma2(y0.y, wB, a0);
                a1 = ffma2(y1.x, wA, a1);  a1 = ffma2(y1.y, wB, a1);
                a2 = ffma2(y2v.x, wA, a2); a2 = ffma2(y2v.y, wB, a2);
                a3 = ffma2(y3.x, wA, a3);  a3 = ffma2(y3.y, wB, a3);
            }
            uint64_t acc[R] = { a0, a1, a2, a3 };
            #pragma unroll
            for (int i = 0; i < R; i++) {
                float v0, v1; unpack2(acc[i], v0, v1);
                v0 = fmaxf(v0, 0.f); v1 = fmaxf(v1, 0.f);
                *(float4*)(hA + (r0 + i) * 192 + cc) = make_float4(v0, v0, v1, v1);
            }
        }
        __syncthreads();   // hA ready CTA-wide

        // ---------- Phase 2: hB = [h1c @ cW2T + cb2 | h1r @ rW2T + rb2] ----------
        {
            uint64_t a0 = b2p, a1 = b2p, a2 = b2p, a3 = b2p;
            if (colg < 2) {
                // complex head: K = 128 over hA[:, 0:128], weight stride 128
                #pragma unroll 4
                for (int k = 0; k < 128; k += 2) {
                    uint64_t wA = ldg64(w2p + k * 128);
                    uint64_t wB = ldg64(w2p + (k + 1) * 128);
                    ulonglong2 h0 = *(const ulonglong2*)&hA[(r0 + 0) * 192 + k];
                    ulonglong2 h1 = *(const ulonglong2*)&hA[(r0 + 1) * 192 + k];
                    ulonglong2 h2v = *(const ulonglong2*)&hA[(r0 + 2) * 192 + k];
                    ulonglong2 h3 = *(const ulonglong2*)&hA[(r0 + 3) * 192 + k];
                    a0 = ffma2(h0.x, wA, a0);  a0 = ffma2(h0.y, wB, a0);
                    a1 = ffma2(h1.x, wA, a1);  a1 = ffma2(h1.y, wB, a1);
                    a2 = ffma2(h2v.x, wA, a2); a2 = ffma2(h2v.y, wB, a2);
                    a3 = ffma2(h3.x, wA, a3);  a3 = ffma2(h3.y, wB, a3);
                }
            } else {
                // real head: K = 64 over hA[:, 128:192], weight stride 64
                #pragma unroll 4
                for (int k = 0; k < 64; k += 2) {
                    uint64_t wA = ldg64(w2p + k * 64);
                    uint64_t wB = ldg64(w2p + (k + 1) * 64);
                    ulonglong2 h0 = *(const ulonglong2*)&hA[(r0 + 0) * 192 + 128 + k];
                    ulonglong2 h1 = *(const ulonglong2*)&hA[(r0 + 1) * 192 + 128 + k];
                    ulonglong2 h2v = *(const ulonglong2*)&hA[(r0 + 2) * 192 + 128 + k];
                    ulonglong2 h3 = *(const ulonglong2*)&hA[(r0 + 3) * 192 + 128 + k];
                    a0 = ffma2(h0.x, wA, a0);  a0 = ffma2(h0.y, wB, a0);
                    a1 = ffma2(h1.x, wA, a1);  a1 = ffma2(h1.y, wB, a1);
                    a2 = ffma2(h2v.x, wA, a2); a2 = ffma2(h2v.y, wB, a2);
                    a3 = ffma2(h3.x, wA, a3);  a3 = ffma2(h3.y, wB, a3);
                }
            }
            int oc = (colg < 2) ? cc : (128 + 2 * lane);
            uint64_t acc[R] = { a0, a1, a2, a3 };
            #pragma unroll
            for (int i = 0; i < R; i++) {
                float v0, v1; unpack2(acc[i], v0, v1);
                *(float4*)(hB + (r0 + i) * 192 + oc) = make_float4(v0, v0, v1, v1);
            }
        }
        __syncthreads();   // hB ready CTA-wide

        // ---------- Phase 3: Koopman update + output (CTA-strided) ----------
        {
            const float* hBf = (const float*)hB;
            const float* y2f = (const float*)y2;
            for (int idx = tid; idx < MROWS * 128; idx += NTH) {
                int m = idx >> 7;
                int i = idx & 127;
                int r = b0 + m;
                int base = m * 192;
                if (i < 64) {
                    float mu = hBf[(base + 2 * i)     << 1];
                    float om = hBf[(base + 2 * i + 1) << 1];
                    float e = __expf(DT * mu);
                    float c = __cosf(DT * om);
                    float s = __sinf(DT * om);
                    float ye = y2f[(base + 2 * i)     << 1];
                    float yo = y2f[(base + 2 * i + 1) << 1];
                    float ne = e * (c * ye - s * yo);
                    float no = e * (s * ye + c * yo);
                    y2[base + 2 * i]     = pack2(ne, ne);
                    y2[base + 2 * i + 1] = pack2(no, no);
                    if (r < B_TOTAL)
                        *(float2*)&out[((size_t)r * T_TOT + t) * KDIM + 2 * i] = make_float2(ne, no);
                } else {
                    int n = i - 64;
                    float re = hBf[(base + 128 + n) << 1];
                    float v  = y2f[(base + 128 + n) << 1] * __expf(DT * re);
                    y2[base + 128 + n] = pack2(v, v);
                    if (r < B_TOTAL)
                        out[((size_t)r * T_TOT + t) * KDIM + 128 + n] = v;
                }
            }
        }
        __syncthreads();   // y2 ready for next step
    }
}

extern "C" void kernel_launch(void* const* d_in, const int* in_sizes, int n_in,
                              void* d_out, int out_size)
{
    const float* x   = (const float*)d_in[0];
    const float* cW1 = (const float*)d_in[1];
    const float* cb1 = (const float*)d_in[2];
    const float* cW2 = (const float*)d_in[3];
    const float* cb2 = (const float*)d_in[4];
    const float* rW1 = (const float*)d_in[5];
    const float* rb1 = (const float*)d_in[6];
    const float* rW2 = (const float*)d_in[7];
    const float* rb2 = (const float*)d_in[8];
    float* out = (float*)d_out;

    pack_weights<<<(192 * 192 + 255) / 256, 256>>>(cW1, cb1, cW2, cb2, rW1, rb1, rW2, rb2);

    cudaFuncSetAttribute(koopman_kernel, cudaFuncAttributeMaxDynamicSharedMemorySize, SMEM_BYTES);
    int grid = (B_TOTAL + MROWS - 1) / MROWS;   // 147
    koopman_kernel<<<grid, NTH, SMEM_BYTES>>>(x, out);
}

// round 7
// speedup vs baseline: 12.4968x; 7.8561x over previous
#include <cuda_runtime.h>
#include <cuda_fp16.h>
#include <cstdint>

#define B_TOTAL  4096
#define T_TOT    64
#define KDIM     192
#define DT       0.01f

#define CTA_ROWS 32
#define NTH      384          // 12 warps = 12 col-tiles of 16
#define NGRID    (B_TOTAL / CTA_ROWS)   // 128

// ---------------- staged weights (fp16 [n][k]) ----------------
__device__ __half g_W1h[192 * 192];   // rows 0-127 = cW1, 128-191 = rW1
__device__ __half g_W2ch[128 * 128];
__device__ __half g_W2rh[64 * 64];
__device__ float  g_b1[192];
__device__ float  g_b2c[128];
__device__ float  g_b2r[64];

__global__ void pack_weights(const float* __restrict__ cW1, const float* __restrict__ cb1,
                             const float* __restrict__ cW2, const float* __restrict__ cb2,
                             const float* __restrict__ rW1, const float* __restrict__ rb1,
                             const float* __restrict__ rW2, const float* __restrict__ rb2)
{
    int i = blockIdx.x * blockDim.x + threadIdx.x;
    if (i < 192 * 192) {
        int n = i / 192, k = i % 192;
        float v = (n < 128) ? cW1[n * 192 + k] : rW1[(n - 128) * 192 + k];
        g_W1h[i] = __float2half_rn(v);
    }
    if (i < 128 * 128) g_W2ch[i] = __float2half_rn(cW2[i]);
    if (i < 64 * 64)   g_W2rh[i] = __float2half_rn(rW2[i]);
    if (i < 192) g_b1[i]  = (i < 128) ? cb1[i] : rb1[i - 128];
    if (i < 128) g_b2c[i] = cb2[i];
    if (i < 64)  g_b2r[i] = rb2[i];
}

// ---------------- warp-level MMA helpers (arch-generic, sm_80+) ----------------
__device__ __forceinline__ uint32_t smem_to_u32(const void* p) {
    uint32_t a;
    asm("{ .reg .u64 t; cvta.to.shared.u64 t, %1; cvt.u32.u64 %0, t; }" : "=r"(a) : "l"(p));
    return a;
}

#define LDSM4(a, addr) \
    asm volatile("ldmatrix.sync.aligned.m8n8.x4.shared.b16 {%0,%1,%2,%3}, [%4];" \
                 : "=r"((a)[0]), "=r"((a)[1]), "=r"((a)[2]), "=r"((a)[3]) : "r"(addr))

#define MMA16816(d, a, b) \
    asm volatile("mma.sync.aligned.m16n8k16.row.col.f32.f16.f16.f32 " \
                 "{%0,%1,%2,%3}, {%4,%5,%6,%7}, {%8,%9}, {%0,%1,%2,%3};" \
                 : "+f"((d)[0]), "+f"((d)[1]), "+f"((d)[2]), "+f"((d)[3]) \
                 : "r"((a)[0]), "r"((a)[1]), "r"((a)[2]), "r"((a)[3]), \
                   "r"((b)[0]), "r"((b)[1]))

// ---------------- SMEM layout (dynamic) ----------------
// yS  : fp32 state  [32][194]  -> 24832 B
// y_h : fp16 state  [32][200]  -> 12800 B (stride 400 B: conflict-free ldmatrix)
// h_h : fp16 hidden [32][200]  -> 12800 B
#define YS_STRIDE 194
#define H_STRIDE  200
#define OFF_YH    24832
#define OFF_HH    37632
#define SMEM_TOTAL 50432

__global__ __launch_bounds__(NTH, 1)
void koopman_mma(const float* __restrict__ x, float* __restrict__ out)
{
    extern __shared__ char smem[];
    float*  yS  = (float*)smem;
    __half* y_h = (__half*)(smem + OFF_YH);
    __half* h_h = (__half*)(smem + OFF_HH);

    const int tid  = threadIdx.x;
    const int lane = tid & 31;
    const int wrp  = tid >> 5;          // 0..11 -> output col-tile n0 = 16*wrp
    const int gid  = lane >> 2;         // 0..7
    const int tig  = lane & 3;          // 0..3
    const int n0   = wrp * 16;
    const bool is_real = (wrp >= 8);    // tiles 8-11 = real head (cols 128-191)
    const int b0   = blockIdx.x * CTA_ROWS;

    // ---- initial state: yS fp32 + y_h fp16 ----
    for (int i = tid; i < CTA_ROWS * KDIM; i += NTH) {
        int r = i / KDIM, k = i % KDIM;
        float v = x[(size_t)(b0 + r) * T_TOT * KDIM + k];
        yS[r * YS_STRIDE + k] = v;
        y_h[r * H_STRIDE + k] = __float2half_rn(v);
    }

    // ---- register-resident B fragments (loaded ONCE) ----
    // mma m16n8k16 B frag: b0 = (k=2*tig, n=gid),(k=2*tig+1, n); b1 = same +8 in k.
    uint32_t b1f[12][4];
    #pragma unroll
    for (int kk = 0; kk < 12; kk++)
        #pragma unroll
        for (int h = 0; h < 2; h++) {
            int n = n0 + 8 * h + gid;
            b1f[kk][2*h]   = *(const uint32_t*)&g_W1h[n * 192 + 16 * kk + 2 * tig];
            b1f[kk][2*h+1] = *(const uint32_t*)&g_W1h[n * 192 + 16 * kk + 2 * tig + 8];
        }
    uint32_t b2f[8][4];
    if (!is_real) {
        #pragma unroll
        for (int kk = 0; kk < 8; kk++)
            #pragma unroll
            for (int h = 0; h < 2; h++) {
                int n = n0 + 8 * h + gid;
                b2f[kk][2*h]   = *(const uint32_t*)&g_W2ch[n * 128 + 16 * kk + 2 * tig];
                b2f[kk][2*h+1] = *(const uint32_t*)&g_W2ch[n * 128 + 16 * kk + 2 * tig + 8];
            }
    } else {
        #pragma unroll
        for (int kk = 0; kk < 4; kk++)
            #pragma unroll
            for (int h = 0; h < 2; h++) {
                int n = n0 - 128 + 8 * h + gid;
                b2f[kk][2*h]   = *(const uint32_t*)&g_W2rh[n * 64 + 16 * kk + 2 * tig];
                b2f[kk][2*h+1] = *(const uint32_t*)&g_W2rh[n * 64 + 16 * kk + 2 * tig + 8];
            }
    }

    // ---- loop-invariant bias pairs for this thread's col pair ----
    float2 b1b[2], b2b[2];
    #pragma unroll
    for (int nt = 0; nt < 2; nt++) {
        int col = n0 + 8 * nt + 2 * tig;
        b1b[nt] = make_float2(g_b1[col], g_b1[col + 1]);
        b2b[nt] = is_real ? make_float2(g_b2r[col - 128], g_b2r[col - 127])
                          : make_float2(g_b2c[col],       g_b2c[col + 1]);
    }

    // ldmatrix per-lane row offset: m0=rows0-7/k0, m1=rows8-15/k0, m2=rows0-7/+16B, m3=rows8-15/+16B
    const uint32_t rowoff = ((((lane >> 3) & 1) * 8 + (lane & 7))) * (H_STRIDE * 2)
                          + (lane >> 4) * 16;
    const uint32_t yh_u = smem_to_u32(y_h) + rowoff;
    const uint32_t hh_u = smem_to_u32(h_h) + rowoff;

    __syncthreads();

    for (int t = 0; t < T_TOT; t++) {
        // ---------- phase 1: h1 = relu(y @ W1^T + b1)  (K=192) ----------
        float d1[2][2][4];
        #pragma unroll
        for (int mt = 0; mt < 2; mt++)
            #pragma unroll
            for (int nt = 0; nt < 2; nt++)
                #pragma unroll
                for (int e = 0; e < 4; e++) d1[mt][nt][e] = 0.f;

        #pragma unroll
        for (int kk = 0; kk < 12; kk++) {
            #pragma unroll
            for (int mt = 0; mt < 2; mt++) {
                uint32_t a[4];
                LDSM4(a, yh_u + mt * (16 * H_STRIDE * 2) + kk * 32);
                MMA16816(d1[mt][0], a, &b1f[kk][0]);
                MMA16816(d1[mt][1], a, &b1f[kk][2]);
            }
        }
        // epilogue 1: bias + relu -> fp16 h_h
        #pragma unroll
        for (int mt = 0; mt < 2; mt++)
            #pragma unroll
            for (int nt = 0; nt < 2; nt++) {
                int col = n0 + 8 * nt + 2 * tig;
                int row = mt * 16 + gid;
                float h0 = fmaxf(d1[mt][nt][0] + b1b[nt].x, 0.f);
                float h1 = fmaxf(d1[mt][nt][1] + b1b[nt].y, 0.f);
                *(__half2*)&h_h[row * H_STRIDE + col] = __floats2half2_rn(h0, h1);
                h0 = fmaxf(d1[mt][nt][2] + b1b[nt].x, 0.f);
                h1 = fmaxf(d1[mt][nt][3] + b1b[nt].y, 0.f);
                *(__half2*)&h_h[(row + 8) * H_STRIDE + col] = __floats2half2_rn(h0, h1);
            }
        __syncthreads();   // h_h visible CTA-wide

        // ---------- phase 2: complex head K=128 (cols 0-127) | real head K=64 (cols 128-191) ----------
        float d2[2][2][4];
        #pragma unroll
        for (int mt = 0; mt < 2; mt++)
            #pragma unroll
            for (int nt = 0; nt < 2; nt++)
                #pragma unroll
                for (int e = 0; e < 4; e++) d2[mt][nt][e] = 0.f;

        if (!is_real) {
            #pragma unroll
            for (int kk = 0; kk < 8; kk++) {
                #pragma unroll
                for (int mt = 0; mt < 2; mt++) {
                    uint32_t a[4];
                    LDSM4(a, hh_u + mt * (16 * H_STRIDE * 2) + kk * 32);
                    MMA16816(d2[mt][0], a, &b2f[kk][0]);
                    MMA16816(d2[mt][1], a, &b2f[kk][2]);
                }
            }
        } else {
            #pragma unroll
            for (int kk = 0; kk < 4; kk++) {
                #pragma unroll
                for (int mt = 0; mt < 2; mt++) {
                    uint32_t a[4];
                    LDSM4(a, hh_u + mt * (16 * H_STRIDE * 2) + 256 + kk * 32);  // +128 halves
                    MMA16816(d2[mt][0], a, &b2f[kk][0]);
                    MMA16816(d2[mt][1], a, &b2f[kk][2]);
                }
            }
        }

        // ---------- phase 3: Koopman update + output (this warp's 16 cols, all 32 rows) ----------
        #pragma unroll
        for (int mt = 0; mt < 2; mt++)
            #pragma unroll
            for (int nt = 0; nt < 2; nt++) {
                int col = n0 + 8 * nt + 2 * tig;
                #pragma unroll
                for (int rr = 0; rr < 2; rr++) {
                    int row = mt * 16 + gid + rr * 8;
                    float v0 = d2[mt][nt][2 * rr]     + b2b[nt].x;
                    float v1 = d2[mt][nt][2 * rr + 1] + b2b[nt].y;
                    float2 yp = *(float2*)&yS[row * YS_STRIDE + col];
                    float o0, o1;
                    if (!is_real) {
                        float e = __expf(DT * v0);
                        float c = __cosf(DT * v1);
                        float s = __sinf(DT * v1);
                        o0 = e * (c * yp.x - s * yp.y);
                        o1 = e * (s * yp.x + c * yp.y);
                    } else {
                        o0 = yp.x * __expf(DT * v0);
                        o1 = yp.y * __expf(DT * v1);
                    }
                    *(float2*)&yS[row * YS_STRIDE + col] = make_float2(o0, o1);
                    *(__half2*)&y_h[row * H_STRIDE + col] = __floats2half2_rn(o0, o1);
                    *(float2*)&out[((size_t)(b0 + row) * T_TOT + t) * KDIM + col] = make_float2(o0, o1);
                }
            }
        __syncthreads();   // y_h/yS updated before next step's phase 1
    }
}

extern "C" void kernel_launch(void* const* d_in, const int* in_sizes, int n_in,
                              void* d_out, int out_size)
{
    const float* x   = (const float*)d_in[0];
    const float* cW1 = (const float*)d_in[1];
    const float* cb1 = (const float*)d_in[2];
    const float* cW2 = (const float*)d_in[3];
    const float* cb2 = (const float*)d_in[4];
    const float* rW1 = (const float*)d_in[5];
    const float* rb1 = (const float*)d_in[6];
    const float* rW2 = (const float*)d_in[7];
    const float* rb2 = (const float*)d_in[8];
    float* out = (float*)d_out;

    pack_weights<<<(192 * 192 + 255) / 256, 256>>>(cW1, cb1, cW2, cb2, rW1, rb1, rW2, rb2);

    cudaFuncSetAttribute(koopman_mma, cudaFuncAttributeMaxDynamicSharedMemorySize, SMEM_TOTAL);
    koopman_mma<<<NGRID, NTH, SMEM_TOTAL>>>(x, out);
}

// round 8
// speedup vs baseline: 17.4334x; 1.3950x over previous
#include <cuda_runtime.h>
#include <cuda_fp16.h>
#include <cstdint>

#define B_TOTAL  4096
#define T_TOT    64
#define KDIM     192
#define DT       0.01f

#define CTA_ROWS 32
#define NTH      384          // 12 warps = 12 col-tiles of 16
#define NGRID    (B_TOTAL / CTA_ROWS)   // 128

// ---------------- staged weights (fp16 [n][k]) ----------------
__device__ __half g_W1h[192 * 192];   // rows 0-127 = cW1, 128-191 = rW1
__device__ __half g_W2ch[128 * 128];
__device__ __half g_W2rh[64 * 64];
__device__ float  g_b1[192];
__device__ float  g_b2c[128];
__device__ float  g_b2r[64];

__global__ void pack_weights(const float* __restrict__ cW1, const float* __restrict__ cb1,
                             const float* __restrict__ cW2, const float* __restrict__ cb2,
                             const float* __restrict__ rW1, const float* __restrict__ rb1,
                             const float* __restrict__ rW2, const float* __restrict__ rb2)
{
    int i = blockIdx.x * blockDim.x + threadIdx.x;
    if (i < 192 * 192) {
        int n = i / 192, k = i % 192;
        float v = (n < 128) ? cW1[n * 192 + k] : rW1[(n - 128) * 192 + k];
        g_W1h[i] = __float2half_rn(v);
    }
    if (i < 128 * 128) g_W2ch[i] = __float2half_rn(cW2[i]);
    if (i < 64 * 64)   g_W2rh[i] = __float2half_rn(rW2[i]);
    if (i < 192) g_b1[i]  = (i < 128) ? cb1[i] : rb1[i - 128];
    if (i < 128) g_b2c[i] = cb2[i];
    if (i < 64)  g_b2r[i] = rb2[i];
}

// ---------------- warp-level MMA helpers (arch-generic, sm_80+) ----------------
__device__ __forceinline__ uint32_t smem_to_u32(const void* p) {
    uint32_t a;
    asm("{ .reg .u64 t; cvta.to.shared.u64 t, %1; cvt.u32.u64 %0, t; }" : "=r"(a) : "l"(p));
    return a;
}

#define LDSM4(a, addr) \
    asm volatile("ldmatrix.sync.aligned.m8n8.x4.shared.b16 {%0,%1,%2,%3}, [%4];" \
                 : "=r"((a)[0]), "=r"((a)[1]), "=r"((a)[2]), "=r"((a)[3]) : "r"(addr))

#define MMA16816(d, a, b) \
    asm volatile("mma.sync.aligned.m16n8k16.row.col.f32.f16.f16.f32 " \
                 "{%0,%1,%2,%3}, {%4,%5,%6,%7}, {%8,%9}, {%0,%1,%2,%3};" \
                 : "+f"((d)[0]), "+f"((d)[1]), "+f"((d)[2]), "+f"((d)[3]) \
                 : "r"((a)[0]), "r"((a)[1]), "r"((a)[2]), "r"((a)[3]), \
                   "r"((b)[0]), "r"((b)[1]))

#define STCG_F2(p, v) \
    asm volatile("st.global.cg.v2.f32 [%0], {%1, %2};" :: "l"(p), "f"((v).x), "f"((v).y) : "memory")

// ---------------- SMEM layout (dynamic) ----------------
// y_h : fp16 state  [32][200] -> 12800 B (stride 400 B: conflict-free ldmatrix)
// h_h : fp16 hidden [32][200] -> 12800 B
#define H_STRIDE  200
#define OFF_HH    12800
#define SMEM_TOTAL 25600

__global__ __launch_bounds__(NTH, 1)
void koopman_mma(const float* __restrict__ x, float* __restrict__ out)
{
    extern __shared__ char smem[];
    __half* y_h = (__half*)smem;
    __half* h_h = (__half*)(smem + OFF_HH);

    const int tid  = threadIdx.x;
    const int lane = tid & 31;
    const int wrp  = tid >> 5;          // 0..11 -> output col-tile n0 = 16*wrp
    const int gid  = lane >> 2;         // 0..7
    const int tig  = lane & 3;          // 0..3
    const int n0   = wrp * 16;
    const bool is_real = (wrp >= 8);    // tiles 8-11 = real head (cols 128-191)
    const int b0   = blockIdx.x * CTA_ROWS;

    // ---- register-resident B fragments (loaded ONCE) ----
    uint32_t b1f[12][4];
    #pragma unroll
    for (int kk = 0; kk < 12; kk++)
        #pragma unroll
        for (int h = 0; h < 2; h++) {
            int n = n0 + 8 * h + gid;
            b1f[kk][2*h]   = *(const uint32_t*)&g_W1h[n * 192 + 16 * kk + 2 * tig];
            b1f[kk][2*h+1] = *(const uint32_t*)&g_W1h[n * 192 + 16 * kk + 2 * tig + 8];
        }
    uint32_t b2f[8][4];
    if (!is_real) {
        #pragma unroll
        for (int kk = 0; kk < 8; kk++)
            #pragma unroll
            for (int h = 0; h < 2; h++) {
                int n = n0 + 8 * h + gid;
                b2f[kk][2*h]   = *(const uint32_t*)&g_W2ch[n * 128 + 16 * kk + 2 * tig];
                b2f[kk][2*h+1] = *(const uint32_t*)&g_W2ch[n * 128 + 16 * kk + 2 * tig + 8];
            }
    } else {
        #pragma unroll
        for (int kk = 0; kk < 4; kk++)
            #pragma unroll
            for (int h = 0; h < 2; h++) {
                int n = n0 - 128 + 8 * h + gid;
                b2f[kk][2*h]   = *(const uint32_t*)&g_W2rh[n * 64 + 16 * kk + 2 * tig];
                b2f[kk][2*h+1] = *(const uint32_t*)&g_W2rh[n * 64 + 16 * kk + 2 * tig + 8];
            }
        #pragma unroll
        for (int kk = 4; kk < 8; kk++)
            #pragma unroll
            for (int e = 0; e < 4; e++) b2f[kk][e] = 0;
    }

    // ---- loop-invariant bias pairs ----
    float2 b1b[2], b2b[2];
    #pragma unroll
    for (int nt = 0; nt < 2; nt++) {
        int col = n0 + 8 * nt + 2 * tig;
        b1b[nt] = make_float2(g_b1[col], g_b1[col + 1]);
        b2b[nt] = is_real ? make_float2(g_b2r[col - 128], g_b2r[col - 127])
                          : make_float2(g_b2c[col],       g_b2c[col + 1]);
    }

    // ---- fp32 state lives in registers: yreg[mt][nt][rr] = y(row, col..col+1) ----
    // row = mt*16 + rr*8 + gid ; col = n0 + nt*8 + 2*tig  (matches D-fragment coords)
    float2 yreg[2][2][2];
    #pragma unroll
    for (int mt = 0; mt < 2; mt++)
        #pragma unroll
        for (int nt = 0; nt < 2; nt++)
            #pragma unroll
            for (int rr = 0; rr < 2; rr++) {
                int row = mt * 16 + rr * 8 + gid;
                int col = n0 + nt * 8 + 2 * tig;
                float2 v = *(const float2*)&x[(size_t)(b0 + row) * T_TOT * KDIM + col];
                yreg[mt][nt][rr] = v;
                *(__half2*)&y_h[row * H_STRIDE + col] = __floats2half2_rn(v.x, v.y);
            }

    // ldmatrix per-lane row offset
    const uint32_t rowoff = ((((lane >> 3) & 1) * 8 + (lane & 7))) * (H_STRIDE * 2)
                          + (lane >> 4) * 16;
    const uint32_t yh_u = smem_to_u32(y_h) + rowoff;
    const uint32_t hh_u = smem_to_u32(h_h) + rowoff;

    __syncthreads();

    for (int t = 0; t < T_TOT; t++) {
        // ---------- phase 1: h1 = relu(y @ W1^T + b1)  (K=192) ----------
        float d1[2][2][4];
        #pragma unroll
        for (int mt = 0; mt < 2; mt++)
            #pragma unroll
            for (int nt = 0; nt < 2; nt++)
                #pragma unroll
                for (int e = 0; e < 4; e++) d1[mt][nt][e] = 0.f;

        #pragma unroll
        for (int kk = 0; kk < 12; kk++) {
            #pragma unroll
            for (int mt = 0; mt < 2; mt++) {
                uint32_t a[4];
                LDSM4(a, yh_u + mt * (16 * H_STRIDE * 2) + kk * 32);
                MMA16816(d1[mt][0], a, &b1f[kk][0]);
                MMA16816(d1[mt][1], a, &b1f[kk][2]);
            }
        }
        // epilogue 1: bias + relu -> fp16 h_h
        #pragma unroll
        for (int mt = 0; mt < 2; mt++)
            #pragma unroll
            for (int nt = 0; nt < 2; nt++) {
                int col = n0 + 8 * nt + 2 * tig;
                int row = mt * 16 + gid;
                float h0 = fmaxf(d1[mt][nt][0] + b1b[nt].x, 0.f);
                float h1 = fmaxf(d1[mt][nt][1] + b1b[nt].y, 0.f);
                *(__half2*)&h_h[row * H_STRIDE + col] = __floats2half2_rn(h0, h1);
                h0 = fmaxf(d1[mt][nt][2] + b1b[nt].x, 0.f);
                h1 = fmaxf(d1[mt][nt][3] + b1b[nt].y, 0.f);
                *(__half2*)&h_h[(row + 8) * H_STRIDE + col] = __floats2half2_rn(h0, h1);
            }
        // split barrier: complex group (warps 0-7) and real group (warps 8-11)
        // are independent through phase 2 (each reads only h cols it wrote).
        if (!is_real) asm volatile("bar.sync 1, 256;" ::: "memory");
        else          asm volatile("bar.sync 2, 128;" ::: "memory");

        // ---------- phase 2 ----------
        float d2[2][2][4];
        #pragma unroll
        for (int mt = 0; mt < 2; mt++)
            #pragma unroll
            for (int nt = 0; nt < 2; nt++)
                #pragma unroll
                for (int e = 0; e < 4; e++) d2[mt][nt][e] = 0.f;

        if (!is_real) {
            #pragma unroll
            for (int kk = 0; kk < 8; kk++) {
                #pragma unroll
                for (int mt = 0; mt < 2; mt++) {
                    uint32_t a[4];
                    LDSM4(a, hh_u + mt * (16 * H_STRIDE * 2) + kk * 32);
                    MMA16816(d2[mt][0], a, &b2f[kk][0]);
                    MMA16816(d2[mt][1], a, &b2f[kk][2]);
                }
            }
        } else {
            #pragma unroll
            for (int kk = 0; kk < 4; kk++) {
                #pragma unroll
                for (int mt = 0; mt < 2; mt++) {
                    uint32_t a[4];
                    LDSM4(a, hh_u + mt * (16 * H_STRIDE * 2) + 256 + kk * 32);
                    MMA16816(d2[mt][0], a, &b2f[kk][0]);
                    MMA16816(d2[mt][1], a, &b2f[kk][2]);
                }
            }
        }

        // ---------- phase 3: Koopman update in registers + stores ----------
        #pragma unroll
        for (int mt = 0; mt < 2; mt++)
            #pragma unroll
            for (int nt = 0; nt < 2; nt++) {
                int col = n0 + 8 * nt + 2 * tig;
                #pragma unroll
                for (int rr = 0; rr < 2; rr++) {
                    int row = mt * 16 + rr * 8 + gid;
                    float v0 = d2[mt][nt][2 * rr]     + b2b[nt].x;
                    float v1 = d2[mt][nt][2 * rr + 1] + b2b[nt].y;
                    float2 yp = yreg[mt][nt][rr];
                    float o0, o1;
                    if (!is_real) {
                        float e = __expf(DT * v0);
                        float c = __cosf(DT * v1);
                        float s = __sinf(DT * v1);
                        o0 = e * (c * yp.x - s * yp.y);
                        o1 = e * (s * yp.x + c * yp.y);
                    } else {
                        o0 = yp.x * __expf(DT * v0);
                        o1 = yp.y * __expf(DT * v1);
                    }
                    yreg[mt][nt][rr] = make_float2(o0, o1);
                    *(__half2*)&y_h[row * H_STRIDE + col] = __floats2half2_rn(o0, o1);
                    float2 ov = make_float2(o0, o1);
                    const float* op = &out[((size_t)(b0 + row) * T_TOT + t) * KDIM + col];
                    STCG_F2(op, ov);
                }
            }
        __syncthreads();   // y_h updated before next step's phase 1
    }
}

extern "C" void kernel_launch(void* const* d_in, const int* in_sizes, int n_in,
                              void* d_out, int out_size)
{
    const float* x   = (const float*)d_in[0];
    const float* cW1 = (const float*)d_in[1];
    const float* cb1 = (const float*)d_in[2];
    const float* cW2 = (const float*)d_in[3];
    const float* cb2 = (const float*)d_in[4];
    const float* rW1 = (const float*)d_in[5];
    const float* rb1 = (const float*)d_in[6];
    const float* rW2 = (const float*)d_in[7];
    const float* rb2 = (const float*)d_in[8];
    float* out = (float*)d_out;

    pack_weights<<<(192 * 192 + 255) / 256, 256>>>(cW1, cb1, cW2, cb2, rW1, rb1, rW2, rb2);

    cudaFuncSetAttribute(koopman_mma, cudaFuncAttributeMaxDynamicSharedMemorySize, SMEM_TOTAL);
    koopman_mma<<<NGRID, NTH, SMEM_TOTAL>>>(x, out);
}

// round 9
// speedup vs baseline: 17.6595x; 1.0130x over previous
#include <cuda_runtime.h>
#include <cuda_fp16.h>
#include <cstdint>

#define B_TOTAL  4096
#define T_TOT    64
#define KDIM     192
#define DT       0.01f

#define CTA_ROWS 32
#define NTH      384          // 12 warps = 12 col-tiles of 16
#define NGRID    (B_TOTAL / CTA_ROWS)   // 128

// ---------------- staged weights (fp16 [n][k]) ----------------
__device__ __half g_W1h[192 * 192];   // rows 0-127 = cW1, 128-191 = rW1
__device__ __half g_W2ch[128 * 128];
__device__ __half g_W2rh[64 * 64];
__device__ float  g_b1[192];
__device__ float  g_b2c[128];
__device__ float  g_b2r[64];

__global__ void pack_weights(const float* __restrict__ cW1, const float* __restrict__ cb1,
                             const float* __restrict__ cW2, const float* __restrict__ cb2,
                             const float* __restrict__ rW1, const float* __restrict__ rb1,
                             const float* __restrict__ rW2, const float* __restrict__ rb2)
{
    int i = blockIdx.x * blockDim.x + threadIdx.x;
    if (i < 192 * 192) {
        int n = i / 192, k = i % 192;
        float v = (n < 128) ? cW1[n * 192 + k] : rW1[(n - 128) * 192 + k];
        g_W1h[i] = __float2half_rn(v);
    }
    if (i < 128 * 128) g_W2ch[i] = __float2half_rn(cW2[i]);
    if (i < 64 * 64)   g_W2rh[i] = __float2half_rn(rW2[i]);
    if (i < 192) g_b1[i]  = (i < 128) ? cb1[i] : rb1[i - 128];
    if (i < 128) g_b2c[i] = cb2[i];
    if (i < 64)  g_b2r[i] = rb2[i];
}

// ---------------- warp-level MMA helpers (arch-generic, sm_80+) ----------------
__device__ __forceinline__ uint32_t smem_to_u32(const void* p) {
    uint32_t a;
    asm("{ .reg .u64 t; cvta.to.shared.u64 t, %1; cvt.u32.u64 %0, t; }" : "=r"(a) : "l"(p));
    return a;
}

#define LDSM4(a, addr) \
    asm volatile("ldmatrix.sync.aligned.m8n8.x4.shared.b16 {%0,%1,%2,%3}, [%4];" \
                 : "=r"((a)[0]), "=r"((a)[1]), "=r"((a)[2]), "=r"((a)[3]) : "r"(addr))

#define MMA16816(d, a, b) \
    asm volatile("mma.sync.aligned.m16n8k16.row.col.f32.f16.f16.f32 " \
                 "{%0,%1,%2,%3}, {%4,%5,%6,%7}, {%8,%9}, {%0,%1,%2,%3};" \
                 : "+f"((d)[0]), "+f"((d)[1]), "+f"((d)[2]), "+f"((d)[3]) \
                 : "r"((a)[0]), "r"((a)[1]), "r"((a)[2]), "r"((a)[3]), \
                   "r"((b)[0]), "r"((b)[1]))

#define STCG_F2(p, v) \
    asm volatile("st.global.cg.v2.f32 [%0], {%1, %2};" :: "l"(p), "f"((v).x), "f"((v).y) : "memory")

// tiny-argument Taylor (|x| <= ~0.03): more accurate than MUFU approximations,
// runs on the FMA pipe instead of the contended MUFU queue.
__device__ __forceinline__ float exp_t(float x) {
    return 1.f + x * (1.f + x * (0.5f + x * (0.16666667f + x * 0.041666668f)));
}
__device__ __forceinline__ float sin_t(float x) { float x2 = x * x; return x * (1.f + x2 * (-0.16666667f + x2 * 0.0083333333f)); }
__device__ __forceinline__ float cos_t(float x) { float x2 = x * x; return 1.f + x2 * (-0.5f + x2 * 0.041666668f); }

// ---------------- SMEM layout (dynamic) ----------------
#define H_STRIDE  200
#define OFF_HH    12800
#define SMEM_TOTAL 25600

__global__ __launch_bounds__(NTH, 1)
void koopman_mma(const float* __restrict__ x, float* __restrict__ out)
{
    extern __shared__ char smem[];
    __half* y_h = (__half*)smem;
    __half* h_h = (__half*)(smem + OFF_HH);

    const int tid  = threadIdx.x;
    const int lane = tid & 31;
    const int wrp  = tid >> 5;          // 0..11 -> output col-tile n0 = 16*wrp
    const int gid  = lane >> 2;         // 0..7
    const int tig  = lane & 3;          // 0..3
    const int n0   = wrp * 16;
    const bool is_real = (wrp >= 8);    // tiles 8-11 = real head (cols 128-191)
    const int b0   = blockIdx.x * CTA_ROWS;

    // ---- register-resident B fragments (loaded ONCE) ----
    uint32_t b1f[12][4];
    #pragma unroll
    for (int kk = 0; kk < 12; kk++)
        #pragma unroll
        for (int h = 0; h < 2; h++) {
            int n = n0 + 8 * h + gid;
            b1f[kk][2*h]   = *(const uint32_t*)&g_W1h[n * 192 + 16 * kk + 2 * tig];
            b1f[kk][2*h+1] = *(const uint32_t*)&g_W1h[n * 192 + 16 * kk + 2 * tig + 8];
        }
    uint32_t b2f[8][4];
    if (!is_real) {
        #pragma unroll
        for (int kk = 0; kk < 8; kk++)
            #pragma unroll
            for (int h = 0; h < 2; h++) {
                int n = n0 + 8 * h + gid;
                b2f[kk][2*h]   = *(const uint32_t*)&g_W2ch[n * 128 + 16 * kk + 2 * tig];
                b2f[kk][2*h+1] = *(const uint32_t*)&g_W2ch[n * 128 + 16 * kk + 2 * tig + 8];
            }
    } else {
        #pragma unroll
        for (int kk = 0; kk < 4; kk++)
            #pragma unroll
            for (int h = 0; h < 2; h++) {
                int n = n0 - 128 + 8 * h + gid;
                b2f[kk][2*h]   = *(const uint32_t*)&g_W2rh[n * 64 + 16 * kk + 2 * tig];
                b2f[kk][2*h+1] = *(const uint32_t*)&g_W2rh[n * 64 + 16 * kk + 2 * tig + 8];
            }
    }

    // ---- loop-invariant bias pairs ----
    float2 b1b[2], b2b[2];
    #pragma unroll
    for (int nt = 0; nt < 2; nt++) {
        int col = n0 + 8 * nt + 2 * tig;
        b1b[nt] = make_float2(g_b1[col], g_b1[col + 1]);
        b2b[nt] = is_real ? make_float2(g_b2r[col - 128], g_b2r[col - 127])
                          : make_float2(g_b2c[col],       g_b2c[col + 1]);
    }

    // ---- fp32 state in registers: yreg[mt][nt][rr] at (row = mt*16+rr*8+gid, col = n0+nt*8+2tig) ----
    float2 yreg[2][2][2];
    #pragma unroll
    for (int mt = 0; mt < 2; mt++)
        #pragma unroll
        for (int nt = 0; nt < 2; nt++)
            #pragma unroll
            for (int rr = 0; rr < 2; rr++) {
                int row = mt * 16 + rr * 8 + gid;
                int col = n0 + nt * 8 + 2 * tig;
                float2 v = *(const float2*)&x[(size_t)(b0 + row) * T_TOT * KDIM + col];
                yreg[mt][nt][rr] = v;
                *(__half2*)&y_h[row * H_STRIDE + col] = __floats2half2_rn(v.x, v.y);
            }

    // per-thread output base pointer (advanced by KDIM per step); store offsets are constants
    float* outp = out + (size_t)(b0 + gid) * T_TOT * KDIM + n0 + 2 * tig;

    // ldmatrix per-lane row offset
    const uint32_t rowoff = ((((lane >> 3) & 1) * 8 + (lane & 7))) * (H_STRIDE * 2)
                          + (lane >> 4) * 16;
    const uint32_t yh_u = smem_to_u32(y_h) + rowoff;
    const uint32_t hh_u = smem_to_u32(h_h) + rowoff;

    __syncthreads();

    for (int t = 0; t < T_TOT; t++) {
        // ---------- phase 1: h1 = relu(y @ W1^T + b1)  (K=192) ----------
        float d1[2][2][4];
        #pragma unroll
        for (int mt = 0; mt < 2; mt++)
            #pragma unroll
            for (int nt = 0; nt < 2; nt++)
                #pragma unroll
                for (int e = 0; e < 4; e++) d1[mt][nt][e] = 0.f;

        #pragma unroll
        for (int kk = 0; kk < 12; kk++) {
            uint32_t a0[4], a1[4];
            LDSM4(a0, yh_u + kk * 32);
            LDSM4(a1, yh_u + (16 * H_STRIDE * 2) + kk * 32);
            MMA16816(d1[0][0], a0, &b1f[kk][0]);
            MMA16816(d1[0][1], a0, &b1f[kk][2]);
            MMA16816(d1[1][0], a1, &b1f[kk][0]);
            MMA16816(d1[1][1], a1, &b1f[kk][2]);
        }
        // epilogue 1: bias + relu -> fp16 h_h
        #pragma unroll
        for (int mt = 0; mt < 2; mt++)
            #pragma unroll
            for (int nt = 0; nt < 2; nt++) {
                int col = n0 + 8 * nt + 2 * tig;
                int row = mt * 16 + gid;
                float h0 = fmaxf(d1[mt][nt][0] + b1b[nt].x, 0.f);
                float h1 = fmaxf(d1[mt][nt][1] + b1b[nt].y, 0.f);
                *(__half2*)&h_h[row * H_STRIDE + col] = __floats2half2_rn(h0, h1);
                h0 = fmaxf(d1[mt][nt][2] + b1b[nt].x, 0.f);
                h1 = fmaxf(d1[mt][nt][3] + b1b[nt].y, 0.f);
                *(__half2*)&h_h[(row + 8) * H_STRIDE + col] = __floats2half2_rn(h0, h1);
            }
        // split barrier: complex (warps 0-7) and real (warps 8-11) groups are
        // independent through phase 2 (each reads only h cols its group wrote).
        if (!is_real) asm volatile("bar.sync 1, 256;" ::: "memory");
        else          asm volatile("bar.sync 2, 128;" ::: "memory");

        // ---------- phase 2 ----------
        float d2[2][2][4];
        #pragma unroll
        for (int mt = 0; mt < 2; mt++)
            #pragma unroll
            for (int nt = 0; nt < 2; nt++)
                #pragma unroll
                for (int e = 0; e < 4; e++) d2[mt][nt][e] = 0.f;

        if (!is_real) {
            #pragma unroll
            for (int kk = 0; kk < 8; kk++) {
                uint32_t a0[4], a1[4];
                LDSM4(a0, hh_u + kk * 32);
                LDSM4(a1, hh_u + (16 * H_STRIDE * 2) + kk * 32);
                MMA16816(d2[0][0], a0, &b2f[kk][0]);
                MMA16816(d2[0][1], a0, &b2f[kk][2]);
                MMA16816(d2[1][0], a1, &b2f[kk][0]);
                MMA16816(d2[1][1], a1, &b2f[kk][2]);
            }
        } else {
            #pragma unroll
            for (int kk = 0; kk < 4; kk++) {
                uint32_t a0[4], a1[4];
                LDSM4(a0, hh_u + 256 + kk * 32);
                LDSM4(a1, hh_u + (16 * H_STRIDE * 2) + 256 + kk * 32);
                MMA16816(d2[0][0], a0, &b2f[kk][0]);
                MMA16816(d2[0][1], a0, &b2f[kk][2]);
                MMA16816(d2[1][0], a1, &b2f[kk][0]);
                MMA16816(d2[1][1], a1, &b2f[kk][2]);
            }
        }

        // ---------- phase 3: Koopman update in registers + stores ----------
        #pragma unroll
        for (int mt = 0; mt < 2; mt++)
            #pragma unroll
            for (int nt = 0; nt < 2; nt++) {
                int col = n0 + 8 * nt + 2 * tig;
                #pragma unroll
                for (int rr = 0; rr < 2; rr++) {
                    int row = mt * 16 + rr * 8 + gid;
                    float v0 = d2[mt][nt][2 * rr]     + b2b[nt].x;
                    float v1 = d2[mt][nt][2 * rr + 1] + b2b[nt].y;
                    float2 yp = yreg[mt][nt][rr];
                    float o0, o1;
                    if (!is_real) {
                        float e = exp_t(DT * v0);
                        float c = cos_t(DT * v1);
                        float s = sin_t(DT * v1);
                        o0 = e * (c * yp.x - s * yp.y);
                        o1 = e * (s * yp.x + c * yp.y);
                    } else {
                        o0 = yp.x * exp_t(DT * v0);
                        o1 = yp.y * exp_t(DT * v1);
                    }
                    yreg[mt][nt][rr] = make_float2(o0, o1);
                    *(__half2*)&y_h[row * H_STRIDE + col] = __floats2half2_rn(o0, o1);
                    float2 ov = make_float2(o0, o1);
                    const float* op = outp + (size_t)(mt * 16 + rr * 8) * T_TOT * KDIM + nt * 8;
                    STCG_F2(op, ov);
                }
            }
        outp += KDIM;
        __syncthreads();   // y_h updated before next step's phase 1
    }
}

extern "C" void kernel_launch(void* const* d_in, const int* in_sizes, int n_in,
                              void* d_out, int out_size)
{
    const float* x   = (const float*)d_in[0];
    const float* cW1 = (const float*)d_in[1];
    const float* cb1 = (const float*)d_in[2];
    const float* cW2 = (const float*)d_in[3];
    const float* cb2 = (const float*)d_in[4];
    const float* rW1 = (const float*)d_in[5];
    const float* rb1 = (const float*)d_in[6];
    const float* rW2 = (const float*)d_in[7];
    const float* rb2 = (const float*)d_in[8];
    float* out = (float*)d_out;

    pack_weights<<<(192 * 192 + 255) / 256, 256>>>(cW1, cb1, cW2, cb2, rW1, rb1, rW2, rb2);

    cudaFuncSetAttribute(koopman_mma, cudaFuncAttributeMaxDynamicSharedMemorySize, SMEM_TOTAL);
    koopman_mma<<<NGRID, NTH, SMEM_TOTAL>>>(x, out);
}